// round 11
// baseline (speedup 1.0000x reference)
#include <cuda_runtime.h>
#include <math.h>
#include <stdint.h>

#define Nn 4096
#define Lt 256
#define TLt 128
#define MUc 0.001f
#define Ac 0.999f          /* 1-mu */
#define OM2MU 0.998f       /* 1-2mu */
#define NM1 4095.0f
#define INV_NM1 (1.0f/4095.0f)
#define EPSF 2.2204460492503131e-16f
#define NNsz ((size_t)Nn*(size_t)Nn)

typedef unsigned long long ull;

// ---- scratch (device globals; no allocations allowed) ----
__device__ __align__(16) uint32_t g_pk[Lt * 128];  // h packed to bits
__device__ float g_rho[Lt];
__device__ float g_cnt[Lt];              // popcount of each h row
__device__ float g_inv[Nn];              // 1 / colsum of clip(a)*clip(b)
__device__ float g_aT[NNsz];             // alpha transposed
__device__ float g_bT[NNsz];             // beta transposed

// ---- packed f32x2 helpers ----
__device__ __forceinline__ ull pk2(float lo, float hi) {
    ull r; asm("mov.b64 %0,{%1,%2};" : "=l"(r) : "f"(lo), "f"(hi)); return r;
}
__device__ __forceinline__ void up2(ull v, float& lo, float& hi) {
    asm("mov.b64 {%0,%1},%2;" : "=f"(lo), "=f"(hi) : "l"(v));
}
__device__ __forceinline__ ull ffma2(ull a, ull b, ull c) {
    ull d; asm("fma.rn.f32x2 %0,%1,%2,%3;" : "=l"(d) : "l"(a), "l"(b), "l"(c)); return d;
}
__device__ __forceinline__ ull fmul2(ull a, ull b) {
    ull d; asm("mul.rn.f32x2 %0,%1,%2;" : "=l"(d) : "l"(a), "l"(b)); return d;
}
__device__ __forceinline__ float frcp_fast(float x) {
    float r; asm("rcp.approx.f32 %0,%1;" : "=f"(r) : "f"(x)); return r;
}
// predicated packed add: if (cond) acc += v
__device__ __forceinline__ void fadd2_if(ull& acc, ull v, uint32_t cond) {
    asm("{\n\t.reg .pred p;\n\tsetp.ne.u32 p, %2, 0;\n\t"
        "@p add.rn.f32x2 %0, %0, %1;\n\t}"
        : "+l"(acc) : "l"(v), "r"(cond));
}

// rho[l] = -expm1(-n_e * m[l]),  n_e = 4*10000/4096 = 9.765625
__global__ void k_rho(float* __restrict__ rho, const float* __restrict__ m) {
    int t = threadIdx.x;
    if (t < Lt) rho[t] = -expm1f(-9.765625f * m[t]);
}

// pack h rows into bitmasks + per-row popcount
__global__ void k_pack(const int* __restrict__ h, uint32_t* __restrict__ pk,
                       float* __restrict__ cnt) {
    __shared__ int wsum[4];
    const int l = blockIdx.x;
    const int w = threadIdx.x;           // 0..127
    const int* row = h + (size_t)l * Nn + w * 32;
    uint32_t v = 0;
#pragma unroll
    for (int b = 0; b < 32; ++b) v |= ((uint32_t)(row[b] & 1)) << b;
    pk[l * 128 + w] = v;
    int c = __popc(v);
#pragma unroll
    for (int off = 16; off; off >>= 1) c += __shfl_xor_sync(0xFFFFFFFFu, c, off);
    if ((w & 31) == 0) wsum[w >> 5] = c;
    __syncthreads();
    if (w == 0) cnt[l] = (float)(wsum[0] + wsum[1] + wsum[2] + wsum[3]);
}

// Theta_j = sum_{i!=j} theta_ij = mu*N + (1-2mu)*same - (1-mu)
__device__ __forceinline__ float4 theta4(uint32_t hj, float c1) {
    const float n0 = 4096.0f - c1;
    const float base = MUc * 4096.0f - Ac;
    float4 th;
    th.x = fmaf(OM2MU, (hj & 1u) ? c1 : n0, base);
    th.y = fmaf(OM2MU, (hj & 2u) ? c1 : n0, base);
    th.z = fmaf(OM2MU, (hj & 4u) ? c1 : n0, base);
    th.w = fmaf(OM2MU, (hj & 8u) ? c1 : n0, base);
    return th;
}

// ---- split reduction. push: 6-SHFL value-split stage1 + STS + barrier.
// pull: LDS + 3 SHFL + 4 broadcast. sbuf = float[2][64] by parity.
__device__ __forceinline__ void red_push(float s0, float s1, float s2, float s3,
                                         float* sbuf, int t, int par) {
    const int lane = t & 31, w = t >> 5;
    const bool hi16 = (lane & 16) != 0, hi8 = (lane & 8) != 0;
    float tA = __shfl_xor_sync(0xFFFFFFFFu, hi16 ? s0 : s2, 16);
    float tB = __shfl_xor_sync(0xFFFFFFFFu, hi16 ? s1 : s3, 16);
    const float x = hi16 ? (s2 + tA) : (s0 + tA);
    const float y = hi16 ? (s3 + tB) : (s1 + tB);
    float tC = __shfl_xor_sync(0xFFFFFFFFu, hi8 ? x : y, 8);
    float z = (hi8 ? y : x) + tC;
    z += __shfl_xor_sync(0xFFFFFFFFu, z, 4);
    z += __shfl_xor_sync(0xFFFFFFFFu, z, 2);
    z += __shfl_xor_sync(0xFFFFFFFFu, z, 1);
    float* buf = sbuf + (par << 6);
    if ((lane & 7) == 0) buf[(w << 2) + (lane >> 3)] = z;
    __syncthreads();
}
__device__ __forceinline__ float4 red_pull(const float* sbuf, int t, int par) {
    const int lane = t & 31;
    const float* buf = sbuf + (par << 6);
    float v = buf[lane] + buf[lane + 32];
    v += __shfl_xor_sync(0xFFFFFFFFu, v, 4);
    v += __shfl_xor_sync(0xFFFFFFFFu, v, 8);
    v += __shfl_xor_sync(0xFFFFFFFFu, v, 16);
    float4 r;
    r.x = __shfl_sync(0xFFFFFFFFu, v, 0, 4);
    r.y = __shfl_sync(0xFFFFFFFFu, v, 1, 4);
    r.z = __shfl_sync(0xFFFFFFFFu, v, 2, 4);
    r.w = __shfl_sync(0xFFFFFFFFu, v, 3, 4);
    return r;
}

// diag fix: subtract diag o from conditional sums (per hn bits) and zero lanes.
// cols j0..j0+3 diag at rows rd0..rd0+3: st[rd0][0].lo, st[rd0+1][0].hi,
// st[rd0+2][1].lo, st[rd0+3][1].hi (rd0 = j0&7, relative to this thread).
__device__ __forceinline__ void diag_fix_q(ull st[8][2], ull& q0, ull& q1,
                                           int rd0, uint32_t hn) {
    float lo, hi, ql, qh;
    up2(q0, ql, qh);
    up2(st[rd0][0], lo, hi);
    if ((hn >> rd0) & 1u) ql -= lo;
    st[rd0][0] = pk2(0.f, hi);
    up2(st[rd0 + 1][0], lo, hi);
    if ((hn >> (rd0 + 1)) & 1u) qh -= hi;
    st[rd0 + 1][0] = pk2(lo, 0.f);
    q0 = pk2(ql, qh);
    up2(q1, ql, qh);
    up2(st[rd0 + 2][1], lo, hi);
    if ((hn >> (rd0 + 2)) & 1u) ql -= lo;
    st[rd0 + 2][1] = pk2(0.f, hi);
    up2(st[rd0 + 3][1], lo, hi);
    if ((hn >> (rd0 + 3)) & 1u) qh -= hi;
    st[rd0 + 3][1] = pk2(lo, 0.f);
    q1 = pk2(ql, qh);
}

// transposed final store: thread owns rows r0..r0+7, cols j0..j0+3
__device__ __forceinline__ void store_T(float* __restrict__ xT, const ull st[8][2],
                                        int j0, int r0) {
#pragma unroll
    for (int c = 0; c < 4; ++c) {
        float v[8];
#pragma unroll
        for (int r = 0; r < 8; ++r) {
            float lo, hi; up2(st[r][c >> 1], lo, hi);
            v[r] = (c & 1) ? hi : lo;
        }
        float* base = xT + (size_t)(j0 + c) * Nn + r0;
        *(float4*)base       = make_float4(v[0], v[1], v[2], v[3]);
        *(float4*)(base + 4) = make_float4(v[4], v[5], v[6], v[7]);
    }
}

// ---------------- forward: analytic S recursion, full-step reduction slack ----
// a_s = theta_s o (a_{s-1}*wp_s + c_s) offdiag;  wp_s = (1-rho_{s-1})/S_{s-1}
// S_s = wp_s*U_s + c_s*Theta_s;  U_s = e0_s*(S_{s-1}-Q_{s-1}) + e1_s*Q_{s-1}
// Q_s = sum_{h_{s+1},i=1, i!=j} a_s  (pushed; pulled next step)
__device__ __forceinline__ void fwd_body(float* __restrict__ aT, int blk,
                                         float* sbuf, float* srho, float* scnt) {
    const int t = threadIdx.x;
    const int j0 = blk << 2;
    const int r0 = t << 3;
    if (t < Lt) { srho[t] = g_rho[t]; scnt[t] = g_cnt[t]; }

    ull st[8][2];
#pragma unroll
    for (int r = 0; r < 8; ++r) { st[r][0] = 0ull; st[r][1] = 0ull; }
    __syncthreads();

    const int wWord = r0 >> 5, wSh = r0 & 31;
    const int jWord = j0 >> 5, jSh = j0 & 31;
    const bool isDiagT = (t == (j0 >> 3));
    const int rd0 = j0 & 7;   // 0 or 4

    float4 Sv = make_float4(1.f, 1.f, 1.f, 1.f);
    ull wp0 = 0ull, wp1 = 0ull, cstp = pk2(INV_NM1, INV_NM1);

    for (int s = 0; s <= TLt; ++s) {
        const uint32_t* row = g_pk + s * 128;
        const uint32_t hb = __ldg(row + wWord) >> wSh;
        const uint32_t hj = (__ldg(row + jWord) >> jSh) & 0xFu;
        const uint32_t hn = (s < TLt) ? (__ldg(row + 128 + wWord) >> wSh) : 0u;
        const float c1 = scnt[s];
        const float4 Th = theta4(hj, c1);

        const float e0a = (hj & 1u) ? MUc : Ac, e1a = (hj & 1u) ? Ac : MUc;
        const float e0b = (hj & 2u) ? MUc : Ac, e1b = (hj & 2u) ? Ac : MUc;
        const float e0c = (hj & 4u) ? MUc : Ac, e1c = (hj & 4u) ? Ac : MUc;
        const float e0d = (hj & 8u) ? MUc : Ac, e1d = (hj & 8u) ? Ac : MUc;
        const ull E0p0 = pk2(e0a, e0b), E1p0 = pk2(e1a, e1b);
        const ull E0p1 = pk2(e0c, e0d), E1p1 = pk2(e1c, e1d);

        if (s == 0) {
            // S_0 analytic: a_0 = theta o pi offdiag
            Sv.x = Th.x * INV_NM1; Sv.y = Th.y * INV_NM1;
            Sv.z = Th.z * INV_NM1; Sv.w = Th.w * INV_NM1;
        } else {
            const float rr = srho[s - 1];
            const float wv = 1.0f - rr;
            const float cs = rr * INV_NM1;
            const float4 Q = red_pull(sbuf, t, (s - 1) & 1);
            float4 wpv;
            wpv.x = wv * frcp_fast(Sv.x); wpv.y = wv * frcp_fast(Sv.y);
            wpv.z = wv * frcp_fast(Sv.z); wpv.w = wv * frcp_fast(Sv.w);
            float4 U;
            U.x = fmaf(e0a, Sv.x - Q.x, e1a * Q.x);
            U.y = fmaf(e0b, Sv.y - Q.y, e1b * Q.y);
            U.z = fmaf(e0c, Sv.z - Q.z, e1c * Q.z);
            U.w = fmaf(e0d, Sv.w - Q.w, e1d * Q.w);
            Sv.x = fmaf(wpv.x, U.x, cs * Th.x);
            Sv.y = fmaf(wpv.y, U.y, cs * Th.y);
            Sv.z = fmaf(wpv.z, U.z, cs * Th.z);
            Sv.w = fmaf(wpv.w, U.w, cs * Th.w);
            wp0 = pk2(wpv.x, wpv.y); wp1 = pk2(wpv.z, wpv.w);
            cstp = pk2(cs, cs);
        }

        ull q0 = 0ull, q1 = 0ull;
#pragma unroll
        for (int r = 0; r < 8; ++r) {
            const bool hi = (hb >> r) & 1u;
            const uint32_t pn = (hn >> r) & 1u;
            const ull o0 = fmul2(hi ? E1p0 : E0p0, ffma2(st[r][0], wp0, cstp));
            const ull o1 = fmul2(hi ? E1p1 : E0p1, ffma2(st[r][1], wp1, cstp));
            st[r][0] = o0; st[r][1] = o1;
            fadd2_if(q0, o0, pn);
            fadd2_if(q1, o1, pn);
        }
        if (isDiagT) diag_fix_q(st, q0, q1, rd0, hn);
        if (s < TLt) {
            float a0, a1, a2, a3;
            up2(q0, a0, a1); up2(q1, a2, a3);
            red_push(a0, a1, a2, a3, sbuf, t, s & 1);
        }
    }
    store_T(aT, st, j0, r0);
}

// ---------------- backward: u-state + fully analytic T recursion --------------
// u_k = theta_k o (K_{k-1} u_{k-1} + r_{k-1}) offdiag
// T_k = e0_k*(SV-QV) + e1_k*QV; SV = K_{k-1} T_{k-1} + r_{k-1}*NM1
// QV = K_{k-1} Q'_{k-1} + r_{k-1}*(c1_k - hj_k); K_k = (1-rho_k')*NM1/T_k
// Q'_k = sum_{h_next,i=1,i!=j} u_k (pushed; pulled next step)
__device__ __forceinline__ void bwd_body(float* __restrict__ bT, int blk,
                                         float* sbuf, float* srho, float* scnt) {
    const int t = threadIdx.x;
    const int j0 = blk << 2;
    const int r0 = t << 3;
    if (t < Lt) { srho[t] = g_rho[t]; scnt[t] = g_cnt[t]; }

    ull st[8][2];
    const ull one2 = pk2(1.0f, 1.0f);
#pragma unroll
    for (int r = 0; r < 8; ++r) { st[r][0] = one2; st[r][1] = one2; }
    __syncthreads();

    const int wWord = r0 >> 5, wSh = r0 & 31;
    const int jWord = j0 >> 5, jSh = j0 & 31;
    const bool isDiagT = (t == (j0 >> 3));
    const int rd0 = j0 & 7;

    float4 Tv = make_float4(1.f, 1.f, 1.f, 1.f);   // T_{k-1}
    float4 Kv = make_float4(0.f, 0.f, 0.f, 0.f);   // K_{k-1} (0 for k=0)
    float rprev = 1.0f;                            // r_{k-1} (1 for k=0 trick)
    ull kp0 = 0ull, kp1 = 0ull, rp = one2;
    float rlast = 0.0f;

    const int NB = Lt - 1 - TLt;  // 127
    for (int k = 0; k < NB; ++k) {
        const int lr = Lt - 1 - k;
        const uint32_t* row = g_pk + lr * 128;
        const uint32_t hb = __ldg(row + wWord) >> wSh;
        const uint32_t hj = (__ldg(row + jWord) >> jSh) & 0xFu;
        const uint32_t hn = (k < NB - 1) ? (__ldg(row - 128 + wWord) >> wSh) : 0u;
        const float c1 = scnt[lr];

        const float e0a = (hj & 1u) ? MUc : Ac, e1a = (hj & 1u) ? Ac : MUc;
        const float e0b = (hj & 2u) ? MUc : Ac, e1b = (hj & 2u) ? Ac : MUc;
        const float e0c = (hj & 4u) ? MUc : Ac, e1c = (hj & 4u) ? Ac : MUc;
        const float e0d = (hj & 8u) ? MUc : Ac, e1d = (hj & 8u) ? Ac : MUc;
        const ull E0p0 = pk2(e0a, e0b), E1p0 = pk2(e1a, e1b);
        const ull E0p1 = pk2(e0c, e0d), E1p1 = pk2(e1c, e1d);

        // loop coefficients for THIS step come from the previous top
        kp0 = pk2(Kv.x, Kv.y); kp1 = pk2(Kv.z, Kv.w); rp = pk2(rprev, rprev);

        float4 Tnew;
        if (k == 0) {
            Tnew = theta4(hj, c1);              // T_0 = Theta(row Lt-1)
        } else {
            const float4 Q = red_pull(sbuf, t, (k - 1) & 1);
            const float a1c = c1 - ((hj & 1u) ? 1.0f : 0.0f);
            const float a2c = c1 - ((hj & 2u) ? 1.0f : 0.0f);
            const float a3c = c1 - ((hj & 4u) ? 1.0f : 0.0f);
            const float a4c = c1 - ((hj & 8u) ? 1.0f : 0.0f);
            float4 SVv, QVv;
            SVv.x = fmaf(Kv.x, Tv.x, rprev * NM1);
            SVv.y = fmaf(Kv.y, Tv.y, rprev * NM1);
            SVv.z = fmaf(Kv.z, Tv.z, rprev * NM1);
            SVv.w = fmaf(Kv.w, Tv.w, rprev * NM1);
            QVv.x = fmaf(Kv.x, Q.x, rprev * a1c);
            QVv.y = fmaf(Kv.y, Q.y, rprev * a2c);
            QVv.z = fmaf(Kv.z, Q.z, rprev * a3c);
            QVv.w = fmaf(Kv.w, Q.w, rprev * a4c);
            Tnew.x = fmaf(e0a, SVv.x - QVv.x, e1a * QVv.x);
            Tnew.y = fmaf(e0b, SVv.y - QVv.y, e1b * QVv.y);
            Tnew.z = fmaf(e0c, SVv.z - QVv.z, e1c * QVv.z);
            Tnew.w = fmaf(e0d, SVv.w - QVv.w, e1d * QVv.w);
        }
        const float rcur = srho[Lt - 2 - k];
        const float ks = (1.0f - rcur) * NM1;
        Kv.x = ks * frcp_fast(Tnew.x); Kv.y = ks * frcp_fast(Tnew.y);
        Kv.z = ks * frcp_fast(Tnew.z); Kv.w = ks * frcp_fast(Tnew.w);
        Tv = Tnew;
        rprev = rcur;
        rlast = rcur;

        ull q0 = 0ull, q1 = 0ull;
#pragma unroll
        for (int r = 0; r < 8; ++r) {
            const bool hi = (hb >> r) & 1u;
            const uint32_t pn = (hn >> r) & 1u;
            const ull o0 = fmul2(hi ? E1p0 : E0p0, ffma2(st[r][0], kp0, rp));
            const ull o1 = fmul2(hi ? E1p1 : E0p1, ffma2(st[r][1], kp1, rp));
            st[r][0] = o0; st[r][1] = o1;
            fadd2_if(q0, o0, pn);
            fadd2_if(q1, o1, pn);
        }
        if (isDiagT) diag_fix_q(st, q0, q1, rd0, hn);
        if (k < NB - 1) {
            float a0, a1, a2, a3;
            up2(q0, a0, a1); up2(q1, a2, a3);
            red_push(a0, a1, a2, a3, sbuf, t, k & 1);
        }
    }
    // final: beta = K_last * u + r_last  (K_last = Kv from last top)
    const ull fk0 = pk2(Kv.x, Kv.y), fk1 = pk2(Kv.z, Kv.w);
    const ull frp = pk2(rlast, rlast);
#pragma unroll
    for (int r = 0; r < 8; ++r) {
        st[r][0] = ffma2(st[r][0], fk0, frp);
        st[r][1] = ffma2(st[r][1], fk1, frp);
    }
    if (isDiagT) {
        st[rd0][0]     &= 0xFFFFFFFF00000000ull;
        st[rd0 + 1][0] &= 0x00000000FFFFFFFFull;
        st[rd0 + 2][1] &= 0xFFFFFFFF00000000ull;
        st[rd0 + 3][1] &= 0x00000000FFFFFFFFull;
    }
    store_T(bT, st, j0, r0);
}

// merged: blocks [0,1024) run forward, [1024,2048) run backward
__global__ void __launch_bounds__(512, 2) k_main(float* __restrict__ aT,
                                                 float* __restrict__ bT) {
    __shared__ __align__(16) float sbuf[128];   // [2 parities][64 partials]
    __shared__ float srho[Lt];
    __shared__ float scnt[Lt];
    if (blockIdx.x < 1024) fwd_body(aT, blockIdx.x, sbuf, srho, scnt);
    else                   bwd_body(bT, blockIdx.x - 1024, sbuf, srho, scnt);
}

// column sums of clip(a)*clip(b) -> inv[j]; block owns 4 rows of a^T/b^T
__global__ void __launch_bounds__(512, 2) k_colsum(const float* __restrict__ aT,
                                                   const float* __restrict__ bT,
                                                   float* __restrict__ inv) {
    __shared__ float4 swarp[16];
    const int t = threadIdx.x;
    const int j0 = blockIdx.x << 2;
    float s[4] = {0.f, 0.f, 0.f, 0.f};
#pragma unroll
    for (int jj = 0; jj < 4; ++jj) {
        const float4* a4 = (const float4*)aT + (size_t)(j0 + jj) * 1024;
        const float4* b4 = (const float4*)bT + (size_t)(j0 + jj) * 1024;
#pragma unroll
        for (int k2 = 0; k2 < 2; ++k2) {
            const int idx = t + (k2 << 9);
            const float4 av = __ldg(a4 + idx);
            const float4 bv = __ldg(b4 + idx);
            s[jj] += __saturatef(av.x) * __saturatef(bv.x)
                   + __saturatef(av.y) * __saturatef(bv.y)
                   + __saturatef(av.z) * __saturatef(bv.z)
                   + __saturatef(av.w) * __saturatef(bv.w);
        }
    }
#pragma unroll
    for (int off = 16; off; off >>= 1) {
        s[0] += __shfl_xor_sync(0xFFFFFFFFu, s[0], off);
        s[1] += __shfl_xor_sync(0xFFFFFFFFu, s[1], off);
        s[2] += __shfl_xor_sync(0xFFFFFFFFu, s[2], off);
        s[3] += __shfl_xor_sync(0xFFFFFFFFu, s[3], off);
    }
    if ((t & 31) == 0) swarp[t >> 5] = make_float4(s[0], s[1], s[2], s[3]);
    __syncthreads();
    if (t == 0) {
        float4 v = swarp[0];
#pragma unroll
        for (int w = 1; w < 16; ++w) {
            float4 q = swarp[w];
            v.x += q.x; v.y += q.y; v.z += q.z; v.w += q.w;
        }
        inv[j0] = 1.0f / v.x; inv[j0 + 1] = 1.0f / v.y;
        inv[j0 + 2] = 1.0f / v.z; inv[j0 + 3] = 1.0f / v.w;
    }
}

// fused epilogue: p + d + alpha/beta std-layout, all from aT/bT tiles.
__global__ void k_out(const float* __restrict__ aT, const float* __restrict__ bT,
                      const float* __restrict__ inv,
                      float* __restrict__ p, float* __restrict__ d,
                      float* __restrict__ aStd, float* __restrict__ bStd) {
    const int bi = blockIdx.y, bj = blockIdx.x;
    if (bj < bi) return;
    __shared__ float PA[32][33], PB[32][33];
    __shared__ float AA[32][33], BA[32][33];
    __shared__ float AB[32][33], BB[32][33];
    const int tx = threadIdx.x & 31;
    const int ty0 = threadIdx.x >> 5;   // 0..7
    const bool diagBlk = (bi == bj);
#pragma unroll
    for (int k2 = 0; k2 < 4; ++k2) {
        const int y = ty0 + (k2 << 3);
        const int ja = (bi << 5) + y;
        const size_t offA = (size_t)ja * Nn + (bj << 5) + tx;
        const float av = __ldg(aT + offA);
        const float bv = __ldg(bT + offA);
        AA[y][tx] = av; BA[y][tx] = bv;
        PA[y][tx] = __saturatef(av) * __saturatef(bv) * __ldg(inv + ja);
        if (!diagBlk) {
            const int jb = (bj << 5) + y;
            const size_t offB = (size_t)jb * Nn + (bi << 5) + tx;
            const float av2 = __ldg(aT + offB);
            const float bv2 = __ldg(bT + offB);
            AB[y][tx] = av2; BB[y][tx] = bv2;
            PB[y][tx] = __saturatef(av2) * __saturatef(bv2) * __ldg(inv + jb);
        }
    }
    __syncthreads();
#pragma unroll
    for (int k2 = 0; k2 < 4; ++k2) {
        const int y = ty0 + (k2 << 3);
        const size_t o1 = (size_t)((bj << 5) + y) * Nn + (bi << 5) + tx;
        p[o1] = PA[tx][y];
        if (aStd) { aStd[o1] = AA[tx][y]; bStd[o1] = BA[tx][y]; }
        if (!diagBlk) {
            const size_t o2 = (size_t)((bi << 5) + y) * Nn + (bj << 5) + tx;
            p[o2] = PB[tx][y];
            if (aStd) { aStd[o2] = AB[tx][y]; bStd[o2] = BB[tx][y]; }
        }
    }
    if (d == nullptr) return;
    __syncthreads();
#pragma unroll
    for (int k2 = 0; k2 < 4; ++k2) {
        const int y = ty0 + (k2 << 3);
        PA[y][tx] = __logf(fmaxf(PA[y][tx], EPSF));
        if (!diagBlk) PB[y][tx] = __logf(fmaxf(PB[y][tx], EPSF));
    }
    __syncthreads();
    float (*LB)[33] = diagBlk ? PA : PB;
#pragma unroll
    for (int k2 = 0; k2 < 4; ++k2) {
        const int y = ty0 + (k2 << 3);
        float dv = -0.5f * (LB[tx][y] + PA[y][tx]);
        if (diagBlk && y == tx) dv = 0.0f;
        d[(size_t)((bi << 5) + y) * Nn + (bj << 5) + tx] = dv;
        if (!diagBlk)
            d[(size_t)((bj << 5) + y) * Nn + (bi << 5) + tx]
                = -0.5f * (PA[tx][y] + LB[y][tx]);
    }
}

extern "C" void kernel_launch(void* const* d_in, const int* in_sizes, int n_in,
                              void* d_out, int out_size) {
    const int* h = (const int*)d_in[0];
    const float* m = (const float*)d_in[1];
    float* out = (float*)d_out;

    void* sym;
    uint32_t* pk; float *rho, *cnt, *aT, *bT, *inv;
    cudaGetSymbolAddress(&sym, g_pk);  pk  = (uint32_t*)sym;
    cudaGetSymbolAddress(&sym, g_rho); rho = (float*)sym;
    cudaGetSymbolAddress(&sym, g_cnt); cnt = (float*)sym;
    cudaGetSymbolAddress(&sym, g_aT);  aT  = (float*)sym;
    cudaGetSymbolAddress(&sym, g_bT);  bT  = (float*)sym;
    cudaGetSymbolAddress(&sym, g_inv); inv = (float*)sym;

    float *pOut, *dOut, *alphaStd, *betaStd;
    size_t osz = (size_t)out_size;
    if (osz >= 4 * NNsz) {
        pOut = out; dOut = out + NNsz;
        alphaStd = out + 2 * NNsz; betaStd = out + 3 * NNsz;
    } else if (osz >= 2 * NNsz) {
        pOut = out; dOut = out + NNsz; alphaStd = nullptr; betaStd = nullptr;
    } else {
        pOut = out; dOut = nullptr; alphaStd = nullptr; betaStd = nullptr;
    }

    k_rho<<<1, 256>>>(rho, m);
    k_pack<<<Lt, 128>>>(h, pk, cnt);
    k_main<<<2048, 512>>>(aT, bT);
    k_colsum<<<Nn / 4, 512>>>(aT, bT, inv);
    dim3 g2(Nn / 32, Nn / 32);
    k_out<<<g2, 256>>>(aT, bT, inv, pOut, dOut, alphaStd, betaStd);
}